// round 8
// baseline (speedup 1.0000x reference)
#include <cuda_runtime.h>
#include <cuda_bf16.h>
#include <math.h>
#include <stdint.h>

// Shapes (fixed by the problem)
#define BB 128
#define SS 1000
#define HH 256
#define SP 1024

// ---------------- scratch (device globals; no allocations allowed) ----------
__device__ float g_bias_attn[BB * 768];
__device__ float g_scores[BB * SP];
__device__ float g_bias_dec[BB * 512];
__device__ float g_oscores[BB * SP];
// Pre-split weights (bf16 hi/lo), K-packed rows
__device__ __nv_bfloat16 g_Whi_a[768 * 512];
__device__ __nv_bfloat16 g_Wlo_a[768 * 512];
__device__ __nv_bfloat16 g_Whi_d[512 * 256];
__device__ __nv_bfloat16 g_Wlo_d[512 * 256];
// Pre-split activations (bf16 hi/lo): [b][s][k], k = 0..255
__device__ __nv_bfloat16 g_Ahi_s[BB * SS * HH];
__device__ __nv_bfloat16 g_Alo_s[BB * SS * HH];
__device__ __nv_bfloat16 g_Ahi_d[BB * SS * HH];
__device__ __nv_bfloat16 g_Alo_d[BB * SS * HH];

// ============================================================================
// Baseline-PTX helpers (compile under compute_103: mma.sync / ldmatrix / cp.async)
// ============================================================================
__device__ __forceinline__ uint32_t smem_u32(const void* p) {
    uint32_t a;
    asm("{ .reg .u64 t; cvta.to.shared.u64 t, %1; cvt.u32.u64 %0, t; }" : "=r"(a) : "l"(p));
    return a;
}
__device__ __forceinline__ void ldm4(uint32_t* r, uint32_t addr) {
    asm volatile("ldmatrix.sync.aligned.m8n8.x4.shared.b16 {%0,%1,%2,%3}, [%4];"
                 : "=r"(r[0]), "=r"(r[1]), "=r"(r[2]), "=r"(r[3]) : "r"(addr));
}
__device__ __forceinline__ void mma_bf16(float* c, const uint32_t* a, uint32_t b0, uint32_t b1) {
    asm volatile("mma.sync.aligned.m16n8k16.row.col.f32.bf16.bf16.f32 "
                 "{%0,%1,%2,%3}, {%4,%5,%6,%7}, {%8,%9}, {%0,%1,%2,%3};"
                 : "+f"(c[0]), "+f"(c[1]), "+f"(c[2]), "+f"(c[3])
                 : "r"(a[0]), "r"(a[1]), "r"(a[2]), "r"(a[3]), "r"(b0), "r"(b1));
}
__device__ __forceinline__ void cpa16(uint32_t dst, const void* src) {
    asm volatile("cp.async.cg.shared.global [%0], [%1], 16;" :: "r"(dst), "l"(src));
}
#define CP_COMMIT() asm volatile("cp.async.commit_group;" ::: "memory")
#define CP_WAIT1()  asm volatile("cp.async.wait_group 1;" ::: "memory")

// ============================================================================
// Kernel 0a: pre-split weights into bf16 hi/lo (K-packed)
// ============================================================================
__global__ __launch_bounds__(256) void k_prep_w(const float* __restrict__ attnW,
                                                const float* __restrict__ decW) {
    const int i = blockIdx.x * 256 + threadIdx.x;
    if (i < 768 * 512) {
        const int j = i >> 9, k = i & 511;
        const float x = attnW[j * 768 + k];
        __nv_bfloat16 h = __float2bfloat16_rn(x);
        g_Whi_a[i] = h;
        g_Wlo_a[i] = __float2bfloat16_rn(x - __bfloat162float(h));
    } else if (i < 768 * 512 + 512 * 256) {
        const int t = i - 768 * 512;
        const int j = t >> 8, k = t & 255;
        const float x = decW[j * 512 + k];
        __nv_bfloat16 h = __float2bfloat16_rn(x);
        g_Whi_d[t] = h;
        g_Wlo_d[t] = __float2bfloat16_rn(x - __bfloat162float(h));
    }
}

// ============================================================================
// Kernel 0b: pre-split static/dynamic into bf16 hi/lo
// ============================================================================
__global__ __launch_bounds__(256) void k_prep_a(const float* __restrict__ statp,
                                                const float* __restrict__ dynp) {
    const long E4 = (long)BB * SS * HH / 4;
    long i = (long)blockIdx.x * 256 + threadIdx.x;
    if (i >= 2 * E4) return;
    const bool dyn = (i >= E4);
    const long j = dyn ? i - E4 : i;
    const float4 x = reinterpret_cast<const float4*>(dyn ? dynp : statp)[j];
    float xs[4] = {x.x, x.y, x.z, x.w};
    unsigned hw[2], lw[2];
#pragma unroll
    for (int p = 0; p < 2; p++) {
        __nv_bfloat16 h0 = __float2bfloat16_rn(xs[2 * p]);
        __nv_bfloat16 h1 = __float2bfloat16_rn(xs[2 * p + 1]);
        __nv_bfloat16 l0 = __float2bfloat16_rn(xs[2 * p] - __bfloat162float(h0));
        __nv_bfloat16 l1 = __float2bfloat16_rn(xs[2 * p + 1] - __bfloat162float(h1));
        hw[p] = (unsigned)__bfloat16_as_ushort(h0) | ((unsigned)__bfloat16_as_ushort(h1) << 16);
        lw[p] = (unsigned)__bfloat16_as_ushort(l0) | ((unsigned)__bfloat16_as_ushort(l1) << 16);
    }
    uint2* hi = reinterpret_cast<uint2*>(dyn ? g_Ahi_d : g_Ahi_s);
    uint2* lo = reinterpret_cast<uint2*>(dyn ? g_Alo_d : g_Alo_s);
    hi[j] = make_uint2(hw[0], hw[1]);
    lo[j] = make_uint2(lw[0], lw[1]);
}

// ============================================================================
// Kernel 1: embed + GRU cell + bias_attn
// ============================================================================
__global__ __launch_bounds__(256) void k_gru(
    const float* __restrict__ din, const float* __restrict__ lasth,
    const float* __restrict__ embW, const float* __restrict__ embb,
    const float* __restrict__ Wih, const float* __restrict__ Whh,
    const float* __restrict__ bih, const float* __restrict__ bhh,
    const float* __restrict__ attnW, float* __restrict__ hid_out, int write_hidden) {
    const int b = blockIdx.x;
    const int t = threadIdx.x;

    __shared__ __align__(16) float emb[HH];
    __shared__ __align__(16) float hold[HH];
    __shared__ __align__(16) float hnew[HH];

    const float d0 = din[b * 2 + 0];
    const float d1 = din[b * 2 + 1];
    emb[t]  = d0 * embW[t * 2 + 0] + d1 * embW[t * 2 + 1] + embb[t];
    hold[t] = lasth[b * HH + t];
    __syncthreads();

    float gx[3], gh[3];
#pragma unroll
    for (int g = 0; g < 3; g++) { gx[g] = bih[g * HH + t]; gh[g] = bhh[g * HH + t]; }
#pragma unroll
    for (int g = 0; g < 3; g++) {
        const float4* wi = reinterpret_cast<const float4*>(Wih + (g * HH + t) * HH);
        const float4* wh = reinterpret_cast<const float4*>(Whh + (g * HH + t) * HH);
        const float4* ev = reinterpret_cast<const float4*>(emb);
        const float4* hv = reinterpret_cast<const float4*>(hold);
        float sx = 0.f, sh = 0.f;
#pragma unroll 4
        for (int k = 0; k < HH / 4; k++) {
            float4 a = wi[k], c = wh[k], e = ev[k], h4 = hv[k];
            sx += a.x * e.x + a.y * e.y + a.z * e.z + a.w * e.w;
            sh += c.x * h4.x + c.y * h4.y + c.z * h4.z + c.w * h4.w;
        }
        gx[g] += sx; gh[g] += sh;
    }

    const float r = 1.f / (1.f + expf(-(gx[0] + gh[0])));
    const float z = 1.f / (1.f + expf(-(gx[1] + gh[1])));
    const float n = tanhf(gx[2] + r * gh[2]);
    const float hv = (1.f - z) * n + z * hold[t];
    hnew[t] = hv;
    if (write_hidden) hid_out[b * HH + t] = hv;
    __syncthreads();

    const float4* hv4 = reinterpret_cast<const float4*>(hnew);
#pragma unroll
    for (int g = 0; g < 3; g++) {
        const int j = g * HH + t;
        const float4* w = reinterpret_cast<const float4*>(attnW + j * 768 + 512);
        float s = 0.f;
#pragma unroll 4
        for (int k = 0; k < HH / 4; k++) {
            float4 ww = w[k], hh = hv4[k];
            s += ww.x * hh.x + ww.y * hh.y + ww.z * hh.z + ww.w * hh.w;
        }
        g_bias_attn[b * 768 + j] = s;
    }
}

// ============================================================================
// Kernel 2/4: fused score GEMM on HMMA (mma.sync bf16, 3-term split, fp32 acc)
//   score[b,s] = sum_j v[j] * tanh( sum_k A[b,s,k]*W[j,k] + bias[b,j] )
// Block 128x128, 4 warps as 2(M)x2(N), warp tile 64x64 (low smem bytes/FMA).
// K chunks of 32 = TWO k16 steps per barrier window (96 mma/warp between
// syncs), 2-stage cp.async buffers, term-major mma ordering (same-accumulator
// ops 8 apart).  Row stride 40 bf16 (80B, conflict-free, 16B-aligned).
// smem = 2 x 40960 + 1KB = 83KB; regs ~215 -> 2 CTAs/SM.
// ============================================================================
#define KCH   32
#define TSTR  40
#define TILE_B (128 * TSTR * 2)   // 10240 bytes
#define AH_OFF 0
#define AL_OFF TILE_B
#define WH_OFF (2 * TILE_B)
#define WL_OFF (3 * TILE_B)
#define BUF_B  (4 * TILE_B)       // 40960 bytes
#define SMEM_GEMM (2 * BUF_B + 1024)

template <int K, int N>
__global__ __launch_bounds__(128, 2) void k_gemm(
    const __nv_bfloat16* __restrict__ Ahi_s, const __nv_bfloat16* __restrict__ Alo_s,
    const __nv_bfloat16* __restrict__ Ahi_d, const __nv_bfloat16* __restrict__ Alo_d,
    const __nv_bfloat16* __restrict__ Whi, const __nv_bfloat16* __restrict__ Wlo,
    const float* __restrict__ bias, const float* __restrict__ v,
    float* __restrict__ scores) {
    constexpr int KC = K / KCH;     // 16 or 8
    constexpr int NT = N / 128;     // 6 or 4
    constexpr int NC = NT * KC;

    extern __shared__ char sm[];
    const uint32_t su = smem_u32(sm);
    float* sred = (float*)(sm + 2 * BUF_B);

    const int tid = threadIdx.x, lane = tid & 31, wid = tid >> 5;
    const int wm = wid & 1, wn = wid >> 1;
    const int b = blockIdx.y, s0 = blockIdx.x * 128;

    // cp.async: thread tid owns row tid of each tile (4x16B per row)
    const long abase = ((long)b * SS + min(s0 + tid, SS - 1)) * HH;

    auto issue = [&](int c) {
        if (c < NC) {
            const int nt = c / KC, kc = c - nt * KC;
            const __nv_bfloat16 *ah, *al;
            int kofs;
            if (K == 512 && kc >= 8) { ah = Ahi_d; al = Alo_d; kofs = (kc - 8) * KCH; }
            else                     { ah = Ahi_s; al = Alo_s; kofs = kc * KCH; }
            const __nv_bfloat16* ph = ah + abase + kofs;
            const __nv_bfloat16* pl = al + abase + kofs;
            const long wrow = (long)(nt * 128 + tid) * K + kc * KCH;
            const uint32_t d = su + (uint32_t)(c & 1) * BUF_B + (uint32_t)(tid * (TSTR * 2));
#pragma unroll
            for (int q = 0; q < 4; q++) {
                cpa16(d + AH_OFF + q * 16, ph + q * 8);
                cpa16(d + AL_OFF + q * 16, pl + q * 8);
                cpa16(d + WH_OFF + q * 16, Whi + wrow + q * 8);
                cpa16(d + WL_OFF + q * 16, Wlo + wrow + q * 8);
            }
        }
    };

    // ldmatrix per-thread base offsets (bytes), within a buffer
    const uint32_t a_sm = (uint32_t)((wm * 64 + (lane & 15)) * (TSTR * 2) + ((lane >> 4) & 1) * 16);
    const uint32_t w_sm = (uint32_t)((wn * 64 + (lane & 7) + ((lane & 16) >> 1)) * (TSTR * 2) + (lane & 8) * 2);

    float part[8];
#pragma unroll
    for (int i = 0; i < 8; i++) part[i] = 0.f;

    issue(0); CP_COMMIT();
    issue(1); CP_COMMIT();

    float acc[4][8][4];

    for (int c = 0; c < NC; c++) {
        const int kc = c % KC;
        const int nt = c / KC;
        if (kc == 0) {
#pragma unroll
            for (int mi = 0; mi < 4; mi++)
#pragma unroll
                for (int j = 0; j < 8; j++)
#pragma unroll
                    for (int q = 0; q < 4; q++) acc[mi][j][q] = 0.f;
        }

        CP_WAIT1();          // chunk c landed (groups c+1 may be in flight)
        __syncthreads();     // cross-thread visibility of buf c%2

        const uint32_t bo = su + (uint32_t)(c & 1) * BUF_B;
#pragma unroll
        for (int ks = 0; ks < 2; ks++) {
            const uint32_t ko = (uint32_t)(ks * 32);  // 16 elems * 2B
            uint32_t ahf[4][4], alf[4][4];
#pragma unroll
            for (int mi = 0; mi < 4; mi++) {
                ldm4(ahf[mi], bo + AH_OFF + a_sm + (uint32_t)(mi * 16 * TSTR * 2) + ko);
                ldm4(alf[mi], bo + AL_OFF + a_sm + (uint32_t)(mi * 16 * TSTR * 2) + ko);
            }
#pragma unroll
            for (int ng = 0; ng < 4; ng++) {
                uint32_t whf[4], wlf[4];
                ldm4(whf, bo + WH_OFF + w_sm + (uint32_t)(ng * 16 * TSTR * 2) + ko);
                ldm4(wlf, bo + WL_OFF + w_sm + (uint32_t)(ng * 16 * TSTR * 2) + ko);
                // term-major: same-accumulator mma are 8 instructions apart
#pragma unroll
                for (int mi = 0; mi < 4; mi++) {
                    mma_bf16(acc[mi][2 * ng],     ahf[mi], whf[0], whf[1]);
                    mma_bf16(acc[mi][2 * ng + 1], ahf[mi], whf[2], whf[3]);
                }
#pragma unroll
                for (int mi = 0; mi < 4; mi++) {
                    mma_bf16(acc[mi][2 * ng],     ahf[mi], wlf[0], wlf[1]);
                    mma_bf16(acc[mi][2 * ng + 1], ahf[mi], wlf[2], wlf[3]);
                }
#pragma unroll
                for (int mi = 0; mi < 4; mi++) {
                    mma_bf16(acc[mi][2 * ng],     alf[mi], whf[0], whf[1]);
                    mma_bf16(acc[mi][2 * ng + 1], alf[mi], whf[2], whf[3]);
                }
            }
        }
        __syncthreads();     // all warps done with buf c%2
        issue(c + 2);        // refill buf c%2
        CP_COMMIT();

        if (kc == KC - 1) {
            // ---- epilogue for this N tile: tanh + v-dot, register-only ----
#pragma unroll
            for (int ng = 0; ng < 4; ng++) {
#pragma unroll
                for (int hf = 0; hf < 2; hf++) {
                    const int j0 = nt * 128 + wn * 64 + ng * 16 + hf * 8 + 2 * (lane & 3);
                    const float2 bv = *reinterpret_cast<const float2*>(&bias[(long)b * N + j0]);
                    const float2 vv = *reinterpret_cast<const float2*>(&v[j0]);
#pragma unroll
                    for (int mi = 0; mi < 4; mi++) {
                        const float* a4 = acc[mi][2 * ng + hf];
                        part[2 * mi + 0] += vv.x * tanhf(a4[0] + bv.x)
                                          + vv.y * tanhf(a4[1] + bv.y);
                        part[2 * mi + 1] += vv.x * tanhf(a4[2] + bv.x)
                                          + vv.y * tanhf(a4[3] + bv.y);
                    }
                }
            }
        }
    }

    // reduce over the 4 lanes sharing each row (lane bits 0,1)
#pragma unroll
    for (int i = 0; i < 8; i++) {
        part[i] += __shfl_xor_sync(0xffffffffu, part[i], 1);
        part[i] += __shfl_xor_sync(0xffffffffu, part[i], 2);
    }
    if ((lane & 3) == 0) {
        const int rq = lane >> 2;  // 0..7
#pragma unroll
        for (int mi = 0; mi < 4; mi++) {
            sred[wn * 128 + wm * 64 + mi * 16 + rq]     = part[2 * mi + 0];
            sred[wn * 128 + wm * 64 + mi * 16 + 8 + rq] = part[2 * mi + 1];
        }
    }
    __syncthreads();
    if (tid < 128) {
        const int s = s0 + tid;
        if (s < SS) scores[b * SP + s] = sred[tid] + sred[128 + tid];
    }
}

// ============================================================================
// Kernel 3: softmax(scores) -> context -> bias_dec
// ============================================================================
__global__ __launch_bounds__(256) void k_ctx(
    const float* __restrict__ statp, const float* __restrict__ decW) {
    const int b = blockIdx.x;
    const int t = threadIdx.x;

    __shared__ float attn[SP];
    __shared__ float red[256];
    __shared__ __align__(16) float ctx[HH];

    float m = -1e30f;
    for (int s = t; s < SS; s += 256) m = fmaxf(m, g_scores[b * SP + s]);
    red[t] = m; __syncthreads();
    for (int o = 128; o; o >>= 1) { if (t < o) red[t] = fmaxf(red[t], red[t + o]); __syncthreads(); }
    m = red[0]; __syncthreads();

    float lsum = 0.f;
    for (int s = t; s < SS; s += 256) {
        const float e = expf(g_scores[b * SP + s] - m);
        attn[s] = e; lsum += e;
    }
    red[t] = lsum; __syncthreads();
    for (int o = 128; o; o >>= 1) { if (t < o) red[t] += red[t + o]; __syncthreads(); }
    const float inv = 1.f / red[0];
    __syncthreads();

    const float* sp = statp + (long)b * SS * HH + t;
    float c0 = 0.f, c1 = 0.f, c2 = 0.f, c3 = 0.f;
    int s = 0;
    for (; s + 3 < SS; s += 4) {
        c0 += attn[s + 0] * sp[(s + 0) * HH];
        c1 += attn[s + 1] * sp[(s + 1) * HH];
        c2 += attn[s + 2] * sp[(s + 2) * HH];
        c3 += attn[s + 3] * sp[(s + 3) * HH];
    }
    for (; s < SS; s++) c0 += attn[s] * sp[s * HH];
    ctx[t] = (c0 + c1 + c2 + c3) * inv;
    __syncthreads();

    const float4* cv = reinterpret_cast<const float4*>(ctx);
#pragma unroll
    for (int g = 0; g < 2; g++) {
        const int j = g * HH + t;
        const float4* w = reinterpret_cast<const float4*>(decW + j * 512 + 256);
        float sacc = 0.f;
#pragma unroll 4
        for (int k = 0; k < HH / 4; k++) {
            float4 ww = w[k], cc = cv[k];
            sacc += ww.x * cc.x + ww.y * cc.y + ww.z * cc.z + ww.w * cc.w;
        }
        g_bias_dec[b * 512 + j] = sacc;
    }
}

// ============================================================================
// Kernel 5: final softmax -> outputs [B,S]
// ============================================================================
__global__ __launch_bounds__(256) void k_softmax_out(float* __restrict__ out) {
    const int b = blockIdx.x;
    const int t = threadIdx.x;
    __shared__ float e_s[SP];
    __shared__ float red[256];

    float m = -1e30f;
    for (int s = t; s < SS; s += 256) m = fmaxf(m, g_oscores[b * SP + s]);
    red[t] = m; __syncthreads();
    for (int o = 128; o; o >>= 1) { if (t < o) red[t] = fmaxf(red[t], red[t + o]); __syncthreads(); }
    m = red[0]; __syncthreads();

    float lsum = 0.f;
    for (int s = t; s < SS; s += 256) {
        const float e = expf(g_oscores[b * SP + s] - m);
        e_s[s] = e; lsum += e;
    }
    red[t] = lsum; __syncthreads();
    for (int o = 128; o; o >>= 1) { if (t < o) red[t] += red[t + o]; __syncthreads(); }
    const float inv = 1.f / red[0];
    __syncthreads();

    for (int s = t; s < SS; s += 256) out[b * SS + s] = e_s[s] * inv;
}

// ============================================================================
// Launch
// ============================================================================
extern "C" void kernel_launch(void* const* d_in, const int* in_sizes, int n_in,
                              void* d_out, int out_size) {
    const float* din   = (const float*)d_in[0];
    const float* lasth = (const float*)d_in[1];
    const float* statp = (const float*)d_in[2];
    const float* dynp  = (const float*)d_in[3];
    const float* embW  = (const float*)d_in[4];
    const float* embb  = (const float*)d_in[5];
    const float* Wih   = (const float*)d_in[6];
    const float* Whh   = (const float*)d_in[7];
    const float* bih   = (const float*)d_in[8];
    const float* bhh   = (const float*)d_in[9];
    const float* attnW = (const float*)d_in[10];
    const float* attnv = (const float*)d_in[11];
    const float* decW  = (const float*)d_in[12];
    const float* decv  = (const float*)d_in[13];
    float* out = (float*)d_out;

    const int write_hidden = (out_size >= BB * SS + BB * HH) ? 1 : 0;
    float* hid_out = out + BB * SS;

    float *p_bias_attn, *p_scores, *p_bias_dec, *p_oscores;
    __nv_bfloat16 *pWhi_a, *pWlo_a, *pWhi_d, *pWlo_d;
    __nv_bfloat16 *pAhi_s, *pAlo_s, *pAhi_d, *pAlo_d;
    cudaGetSymbolAddress((void**)&p_bias_attn, g_bias_attn);
    cudaGetSymbolAddress((void**)&p_scores,    g_scores);
    cudaGetSymbolAddress((void**)&p_bias_dec,  g_bias_dec);
    cudaGetSymbolAddress((void**)&p_oscores,   g_oscores);
    cudaGetSymbolAddress((void**)&pWhi_a, g_Whi_a);
    cudaGetSymbolAddress((void**)&pWlo_a, g_Wlo_a);
    cudaGetSymbolAddress((void**)&pWhi_d, g_Whi_d);
    cudaGetSymbolAddress((void**)&pWlo_d, g_Wlo_d);
    cudaGetSymbolAddress((void**)&pAhi_s, g_Ahi_s);
    cudaGetSymbolAddress((void**)&pAlo_s, g_Alo_s);
    cudaGetSymbolAddress((void**)&pAhi_d, g_Ahi_d);
    cudaGetSymbolAddress((void**)&pAlo_d, g_Alo_d);

    cudaFuncSetAttribute(k_gemm<512, 768>, cudaFuncAttributeMaxDynamicSharedMemorySize, SMEM_GEMM);
    cudaFuncSetAttribute(k_gemm<256, 512>, cudaFuncAttributeMaxDynamicSharedMemorySize, SMEM_GEMM);

    const int prep_w_blocks = (768 * 512 + 512 * 256 + 255) / 256;
    k_prep_w<<<prep_w_blocks, 256>>>(attnW, decW);

    const long E4 = (long)BB * SS * HH / 4;
    const int prep_a_blocks = (int)((2 * E4 + 255) / 256);
    k_prep_a<<<prep_a_blocks, 256>>>(statp, dynp);

    k_gru<<<BB, 256>>>(din, lasth, embW, embb, Wih, Whh, bih, bhh, attnW,
                       hid_out, write_hidden);

    dim3 g(8, BB);  // 8 M-tiles of 128 rows, 128 batches
    k_gemm<512, 768><<<g, 128, SMEM_GEMM>>>(pAhi_s, pAlo_s, pAhi_d, pAlo_d,
                                            pWhi_a, pWlo_a, p_bias_attn, attnv, p_scores);

    k_ctx<<<BB, 256>>>(statp, decW);

    k_gemm<256, 512><<<g, 128, SMEM_GEMM>>>(pAhi_s, pAlo_s, pAhi_s, pAlo_s,
                                            pWhi_d, pWlo_d, p_bias_dec, decv, p_oscores);

    k_softmax_out<<<BB, 256>>>(out);
}

// round 9
// speedup vs baseline: 1.5151x; 1.5151x over previous
#include <cuda_runtime.h>
#include <cuda_fp16.h>
#include <math.h>
#include <stdint.h>

// Shapes (fixed by the problem)
#define BB 128
#define SS 1000
#define HH 256
#define SP 1024

// ---------------- scratch (device globals; no allocations allowed) ----------
__device__ float g_bias_attn[BB * 768];
__device__ float g_scores[BB * SP];
__device__ float g_bias_dec[BB * 512];
__device__ float g_oscores[BB * SP];
// Pre-split weights (fp16 hi/lo), K-packed rows
__device__ __half g_Wh_a[768 * 512];
__device__ __half g_Wl_a[768 * 512];
__device__ __half g_Wh_d[512 * 256];
__device__ __half g_Wl_d[512 * 256];
// Activations as single fp16: [b][s][k]
__device__ __half g_A16_s[BB * SS * HH];
__device__ __half g_A16_d[BB * SS * HH];

// ============================================================================
// Baseline-PTX helpers (compile under compute_103: mma.sync / ldmatrix / cp.async)
// ============================================================================
__device__ __forceinline__ uint32_t smem_u32(const void* p) {
    uint32_t a;
    asm("{ .reg .u64 t; cvta.to.shared.u64 t, %1; cvt.u32.u64 %0, t; }" : "=r"(a) : "l"(p));
    return a;
}
__device__ __forceinline__ void ldm4(uint32_t* r, uint32_t addr) {
    asm volatile("ldmatrix.sync.aligned.m8n8.x4.shared.b16 {%0,%1,%2,%3}, [%4];"
                 : "=r"(r[0]), "=r"(r[1]), "=r"(r[2]), "=r"(r[3]) : "r"(addr));
}
__device__ __forceinline__ void mma_f16(float* c, const uint32_t* a, uint32_t b0, uint32_t b1) {
    asm volatile("mma.sync.aligned.m16n8k16.row.col.f32.f16.f16.f32 "
                 "{%0,%1,%2,%3}, {%4,%5,%6,%7}, {%8,%9}, {%0,%1,%2,%3};"
                 : "+f"(c[0]), "+f"(c[1]), "+f"(c[2]), "+f"(c[3])
                 : "r"(a[0]), "r"(a[1]), "r"(a[2]), "r"(a[3]), "r"(b0), "r"(b1));
}
__device__ __forceinline__ void cpa16(uint32_t dst, const void* src) {
    asm volatile("cp.async.cg.shared.global [%0], [%1], 16;" :: "r"(dst), "l"(src));
}
#define CP_COMMIT() asm volatile("cp.async.commit_group;" ::: "memory")
#define CP_WAIT1()  asm volatile("cp.async.wait_group 1;" ::: "memory")

// ============================================================================
// Kernel 0a: pre-split weights into fp16 hi/lo (K-packed)
// ============================================================================
__global__ __launch_bounds__(256) void k_prep_w(const float* __restrict__ attnW,
                                                const float* __restrict__ decW) {
    const int i = blockIdx.x * 256 + threadIdx.x;
    if (i < 768 * 512) {
        const int j = i >> 9, k = i & 511;
        const float x = attnW[j * 768 + k];
        __half h = __float2half_rn(x);
        g_Wh_a[i] = h;
        g_Wl_a[i] = __float2half_rn(x - __half2float(h));
    } else if (i < 768 * 512 + 512 * 256) {
        const int t = i - 768 * 512;
        const int j = t >> 8, k = t & 255;
        const float x = decW[j * 512 + k];
        __half h = __float2half_rn(x);
        g_Wh_d[t] = h;
        g_Wl_d[t] = __float2half_rn(x - __half2float(h));
    }
}

// ============================================================================
// Kernel 0b: convert static/dynamic to fp16 (single array each)
// ============================================================================
__global__ __launch_bounds__(256) void k_prep_a(const float* __restrict__ statp,
                                                const float* __restrict__ dynp) {
    const long E4 = (long)BB * SS * HH / 4;   // float4 count per tensor
    long i = (long)blockIdx.x * 256 + threadIdx.x;
    if (i >= 2 * E4) return;
    const bool dyn = (i >= E4);
    const long j = dyn ? i - E4 : i;
    const float4 x = reinterpret_cast<const float4*>(dyn ? dynp : statp)[j];
    __half2 lo = __floats2half2_rn(x.x, x.y);
    __half2 hi = __floats2half2_rn(x.z, x.w);
    uint2* dst = reinterpret_cast<uint2*>(dyn ? g_A16_d : g_A16_s);
    dst[j] = make_uint2(*(const unsigned*)&lo, *(const unsigned*)&hi);
}

// ============================================================================
// Kernel 1: embed + GRU cell + bias_attn  (fp32, unchanged)
// ============================================================================
__global__ __launch_bounds__(256) void k_gru(
    const float* __restrict__ din, const float* __restrict__ lasth,
    const float* __restrict__ embW, const float* __restrict__ embb,
    const float* __restrict__ Wih, const float* __restrict__ Whh,
    const float* __restrict__ bih, const float* __restrict__ bhh,
    const float* __restrict__ attnW, float* __restrict__ hid_out, int write_hidden) {
    const int b = blockIdx.x;
    const int t = threadIdx.x;

    __shared__ __align__(16) float emb[HH];
    __shared__ __align__(16) float hold[HH];
    __shared__ __align__(16) float hnew[HH];

    const float d0 = din[b * 2 + 0];
    const float d1 = din[b * 2 + 1];
    emb[t]  = d0 * embW[t * 2 + 0] + d1 * embW[t * 2 + 1] + embb[t];
    hold[t] = lasth[b * HH + t];
    __syncthreads();

    float gx[3], gh[3];
#pragma unroll
    for (int g = 0; g < 3; g++) { gx[g] = bih[g * HH + t]; gh[g] = bhh[g * HH + t]; }
#pragma unroll
    for (int g = 0; g < 3; g++) {
        const float4* wi = reinterpret_cast<const float4*>(Wih + (g * HH + t) * HH);
        const float4* wh = reinterpret_cast<const float4*>(Whh + (g * HH + t) * HH);
        const float4* ev = reinterpret_cast<const float4*>(emb);
        const float4* hv = reinterpret_cast<const float4*>(hold);
        float sx = 0.f, sh = 0.f;
#pragma unroll 4
        for (int k = 0; k < HH / 4; k++) {
            float4 a = wi[k], c = wh[k], e = ev[k], h4 = hv[k];
            sx += a.x * e.x + a.y * e.y + a.z * e.z + a.w * e.w;
            sh += c.x * h4.x + c.y * h4.y + c.z * h4.z + c.w * h4.w;
        }
        gx[g] += sx; gh[g] += sh;
    }

    const float r = 1.f / (1.f + expf(-(gx[0] + gh[0])));
    const float z = 1.f / (1.f + expf(-(gx[1] + gh[1])));
    const float n = tanhf(gx[2] + r * gh[2]);
    const float hv = (1.f - z) * n + z * hold[t];
    hnew[t] = hv;
    if (write_hidden) hid_out[b * HH + t] = hv;
    __syncthreads();

    const float4* hv4 = reinterpret_cast<const float4*>(hnew);
#pragma unroll
    for (int g = 0; g < 3; g++) {
        const int j = g * HH + t;
        const float4* w = reinterpret_cast<const float4*>(attnW + j * 768 + 512);
        float s = 0.f;
#pragma unroll 4
        for (int k = 0; k < HH / 4; k++) {
            float4 ww = w[k], hh = hv4[k];
            s += ww.x * hh.x + ww.y * hh.y + ww.z * hh.z + ww.w * hh.w;
        }
        g_bias_attn[b * 768 + j] = s;
    }
}

// ============================================================================
// Kernel 2/4: fused score GEMM on HMMA (fp16 2-term split, fp32 accum)
//   score[b,s] = sum_j v[j] * tanh( sum_k A[b,s,k]*W[j,k] + bias[b,j] )
// R6 skeleton: block 128 rows x full N, 8 warps = 4(M) x 2(N), warp tile 32x64.
// fp16: A single + W hi/lo => 2 mma terms (-33% tensor work), 3 smem tiles
// (-25% traffic).  K chunks of 64 (4 k16 steps per barrier window), 2-stage
// cp.async, row stride 72 fp16 (144B, conflict-free).  smem 110.6KB -> 2 CTA/SM.
// ============================================================================
#define KCH   64
#define TSTR  72
#define TILE_B (128 * TSTR * 2)   // 18432 bytes
#define A_OFF  0
#define WH_OFF TILE_B
#define WL_OFF (2 * TILE_B)
#define BUF_B  (3 * TILE_B)       // 55296 bytes
#define SMEM_GEMM (2 * BUF_B + 1024)

template <int K, int N>
__global__ __launch_bounds__(256, 2) void k_gemm(
    const __half* __restrict__ A16_s, const __half* __restrict__ A16_d,
    const __half* __restrict__ Wh, const __half* __restrict__ Wl,
    const float* __restrict__ bias, const float* __restrict__ v,
    float* __restrict__ scores) {
    constexpr int KC = K / KCH;     // 8 or 4
    constexpr int NT = N / 128;     // 6 or 4
    constexpr int NC = NT * KC;

    extern __shared__ char sm[];
    const uint32_t su = smem_u32(sm);
    float* sred = (float*)(sm + 2 * BUF_B);

    const int tid = threadIdx.x, lane = tid & 31, wid = tid >> 5;
    const int wm = wid & 3, wn = wid >> 2;
    const int b = blockIdx.y, s0 = blockIdx.x * 128;

    // cp.async: thread covers (row = tid/2, 32-elem half = tid&1); 4x16B each
    const int cr = tid >> 1, ch = tid & 1;
    const long abase = ((long)b * SS + min(s0 + cr, SS - 1)) * HH + ch * 32;
    const uint32_t cd = (uint32_t)((cr * TSTR + ch * 32) * 2);

    auto issue = [&](int c) {
        if (c < NC) {
            const int nt = c / KC, kc = c - nt * KC;
            const __half* asrc;
            int kofs;
            if (K == 512 && kc >= 4) { asrc = A16_d; kofs = (kc - 4) * KCH; }
            else                     { asrc = A16_s; kofs = kc * KCH; }
            const __half* pa = asrc + abase + kofs;
            const long wrow = (long)(nt * 128 + cr) * K + kc * KCH + ch * 32;
            const uint32_t d = su + (uint32_t)(c & 1) * BUF_B + cd;
#pragma unroll
            for (int q = 0; q < 4; q++) {
                cpa16(d + A_OFF + q * 16,  pa + q * 8);
                cpa16(d + WH_OFF + q * 16, Wh + wrow + q * 8);
                cpa16(d + WL_OFF + q * 16, Wl + wrow + q * 8);
            }
        }
    };

    // ldmatrix per-thread base offsets (bytes), within a buffer
    const uint32_t a_sm = (uint32_t)((wm * 32 + (lane & 15)) * (TSTR * 2) + ((lane >> 4) & 1) * 16);
    const uint32_t w_sm = (uint32_t)((wn * 64 + (lane & 7) + ((lane & 16) >> 1)) * (TSTR * 2) + (lane & 8) * 2);

    float part[4] = {0.f, 0.f, 0.f, 0.f};

    issue(0); CP_COMMIT();
    issue(1); CP_COMMIT();

    float acc[2][8][4];

    for (int c = 0; c < NC; c++) {
        const int kc = c % KC;
        const int nt = c / KC;
        if (kc == 0) {
#pragma unroll
            for (int i = 0; i < 2; i++)
#pragma unroll
                for (int j = 0; j < 8; j++)
#pragma unroll
                    for (int q = 0; q < 4; q++) acc[i][j][q] = 0.f;
        }

        CP_WAIT1();
        __syncthreads();

        const uint32_t bo = su + (uint32_t)(c & 1) * BUF_B;
#pragma unroll
        for (int ks = 0; ks < 4; ks++) {
            const uint32_t ko = (uint32_t)(ks * 32);  // 16 elems * 2B
            uint32_t af[2][4];
#pragma unroll
            for (int mi = 0; mi < 2; mi++)
                ldm4(af[mi], bo + A_OFF + a_sm + (uint32_t)(mi * 16 * TSTR * 2) + ko);
#pragma unroll
            for (int ng = 0; ng < 4; ng++) {
                uint32_t whf[4], wlf[4];
                ldm4(whf, bo + WH_OFF + w_sm + (uint32_t)(ng * 16 * TSTR * 2) + ko);
                ldm4(wlf, bo + WL_OFF + w_sm + (uint32_t)(ng * 16 * TSTR * 2) + ko);
#pragma unroll
                for (int mi = 0; mi < 2; mi++) {
                    mma_f16(acc[mi][2 * ng],     af[mi], whf[0], whf[1]);
                    mma_f16(acc[mi][2 * ng + 1], af[mi], whf[2], whf[3]);
                }
#pragma unroll
                for (int mi = 0; mi < 2; mi++) {
                    mma_f16(acc[mi][2 * ng],     af[mi], wlf[0], wlf[1]);
                    mma_f16(acc[mi][2 * ng + 1], af[mi], wlf[2], wlf[3]);
                }
            }
        }
        __syncthreads();
        issue(c + 2);
        CP_COMMIT();

        if (kc == KC - 1) {
            // ---- epilogue for this N tile: tanh + v-dot, register-only ----
            const int jb = nt * 128 + wn * 64 + 2 * (lane & 3);
#pragma unroll
            for (int n8 = 0; n8 < 8; n8++) {
                const int j = jb + n8 * 8;
                const float2 bv = *reinterpret_cast<const float2*>(&bias[(long)b * N + j]);
                const float2 vv = *reinterpret_cast<const float2*>(&v[j]);
#pragma unroll
                for (int mi = 0; mi < 2; mi++) {
                    part[mi * 2 + 0] += vv.x * tanhf(acc[mi][n8][0] + bv.x)
                                      + vv.y * tanhf(acc[mi][n8][1] + bv.y);
                    part[mi * 2 + 1] += vv.x * tanhf(acc[mi][n8][2] + bv.x)
                                      + vv.y * tanhf(acc[mi][n8][3] + bv.y);
                }
            }
        }
    }

    // reduce across the 4 lanes sharing a row (lane bits 0,1)
#pragma unroll
    for (int i = 0; i < 4; i++) {
        part[i] += __shfl_xor_sync(0xffffffffu, part[i], 1);
        part[i] += __shfl_xor_sync(0xffffffffu, part[i], 2);
    }
    if ((lane & 3) == 0) {
        const int r = lane >> 2;
        const int base = wn * 128 + wm * 32;
        sred[base + r]      = part[0];
        sred[base + r + 8]  = part[1];
        sred[base + r + 16] = part[2];
        sred[base + r + 24] = part[3];
    }
    __syncthreads();
    if (tid < 128) {
        const int s = s0 + tid;
        if (s < SS) scores[b * SP + s] = sred[tid] + sred[128 + tid];
    }
}

// ============================================================================
// Kernel 3: softmax(scores) -> context -> bias_dec  (fp32, unchanged)
// ============================================================================
__global__ __launch_bounds__(256) void k_ctx(
    const float* __restrict__ statp, const float* __restrict__ decW) {
    const int b = blockIdx.x;
    const int t = threadIdx.x;

    __shared__ float attn[SP];
    __shared__ float red[256];
    __shared__ __align__(16) float ctx[HH];

    float m = -1e30f;
    for (int s = t; s < SS; s += 256) m = fmaxf(m, g_scores[b * SP + s]);
    red[t] = m; __syncthreads();
    for (int o = 128; o; o >>= 1) { if (t < o) red[t] = fmaxf(red[t], red[t + o]); __syncthreads(); }
    m = red[0]; __syncthreads();

    float lsum = 0.f;
    for (int s = t; s < SS; s += 256) {
        const float e = expf(g_scores[b * SP + s] - m);
        attn[s] = e; lsum += e;
    }
    red[t] = lsum; __syncthreads();
    for (int o = 128; o; o >>= 1) { if (t < o) red[t] += red[t + o]; __syncthreads(); }
    const float inv = 1.f / red[0];
    __syncthreads();

    const float* sp = statp + (long)b * SS * HH + t;
    float c0 = 0.f, c1 = 0.f, c2 = 0.f, c3 = 0.f;
    int s = 0;
    for (; s + 3 < SS; s += 4) {
        c0 += attn[s + 0] * sp[(s + 0) * HH];
        c1 += attn[s + 1] * sp[(s + 1) * HH];
        c2 += attn[s + 2] * sp[(s + 2) * HH];
        c3 += attn[s + 3] * sp[(s + 3) * HH];
    }
    for (; s < SS; s++) c0 += attn[s] * sp[s * HH];
    ctx[t] = (c0 + c1 + c2 + c3) * inv;
    __syncthreads();

    const float4* cv = reinterpret_cast<const float4*>(ctx);
#pragma unroll
    for (int g = 0; g < 2; g++) {
        const int j = g * HH + t;
        const float4* w = reinterpret_cast<const float4*>(decW + j * 512 + 256);
        float sacc = 0.f;
#pragma unroll 4
        for (int k = 0; k < HH / 4; k++) {
            float4 ww = w[k], cc = cv[k];
            sacc += ww.x * cc.x + ww.y * cc.y + ww.z * cc.z + ww.w * cc.w;
        }
        g_bias_dec[b * 512 + j] = sacc;
    }
}

// ============================================================================
// Kernel 5: final softmax -> outputs [B,S]
// ============================================================================
__global__ __launch_bounds__(256) void k_softmax_out(float* __restrict__ out) {
    const int b = blockIdx.x;
    const int t = threadIdx.x;
    __shared__ float e_s[SP];
    __shared__ float red[256];

    float m = -1e30f;
    for (int s = t; s < SS; s += 256) m = fmaxf(m, g_oscores[b * SP + s]);
    red[t] = m; __syncthreads();
    for (int o = 128; o; o >>= 1) { if (t < o) red[t] = fmaxf(red[t], red[t + o]); __syncthreads(); }
    m = red[0]; __syncthreads();

    float lsum = 0.f;
    for (int s = t; s < SS; s += 256) {
        const float e = expf(g_oscores[b * SP + s] - m);
        e_s[s] = e; lsum += e;
    }
    red[t] = lsum; __syncthreads();
    for (int o = 128; o; o >>= 1) { if (t < o) red[t] += red[t + o]; __syncthreads(); }
    const float inv = 1.f / red[0];
    __syncthreads();

    for (int s = t; s < SS; s += 256) out[b * SS + s] = e_s[s] * inv;
}

// ============================================================================
// Launch
// ============================================================================
extern "C" void kernel_launch(void* const* d_in, const int* in_sizes, int n_in,
                              void* d_out, int out_size) {
    const float* din   = (const float*)d_in[0];
    const float* lasth = (const float*)d_in[1];
    const float* statp = (const float*)d_in[2];
    const float* dynp  = (const float*)d_in[3];
    const float* embW  = (const float*)d_in[4];
    const float* embb  = (const float*)d_in[5];
    const float* Wih   = (const float*)d_in[6];
    const float* Whh   = (const float*)d_in[7];
    const float* bih   = (const float*)d_in[8];
    const float* bhh   = (const float*)d_in[9];
    const float* attnW = (const float*)d_in[10];
    const float* attnv = (const float*)d_in[11];
    const float* decW  = (const float*)d_in[12];
    const float* decv  = (const float*)d_in[13];
    float* out = (float*)d_out;

    const int write_hidden = (out_size >= BB * SS + BB * HH) ? 1 : 0;
    float* hid_out = out + BB * SS;

    float *p_bias_attn, *p_scores, *p_bias_dec, *p_oscores;
    __half *pWh_a, *pWl_a, *pWh_d, *pWl_d, *pA16_s, *pA16_d;
    cudaGetSymbolAddress((void**)&p_bias_attn, g_bias_attn);
    cudaGetSymbolAddress((void**)&p_scores,    g_scores);
    cudaGetSymbolAddress((void**)&p_bias_dec,  g_bias_dec);
    cudaGetSymbolAddress((void**)&p_oscores,   g_oscores);
    cudaGetSymbolAddress((void**)&pWh_a, g_Wh_a);
    cudaGetSymbolAddress((void**)&pWl_a, g_Wl_a);
    cudaGetSymbolAddress((void**)&pWh_d, g_Wh_d);
    cudaGetSymbolAddress((void**)&pWl_d, g_Wl_d);
    cudaGetSymbolAddress((void**)&pA16_s, g_A16_s);
    cudaGetSymbolAddress((void**)&pA16_d, g_A16_d);

    cudaFuncSetAttribute(k_gemm<512, 768>, cudaFuncAttributeMaxDynamicSharedMemorySize, SMEM_GEMM);
    cudaFuncSetAttribute(k_gemm<256, 512>, cudaFuncAttributeMaxDynamicSharedMemorySize, SMEM_GEMM);

    const int prep_w_blocks = (768 * 512 + 512 * 256 + 255) / 256;
    k_prep_w<<<prep_w_blocks, 256>>>(attnW, decW);

    const long E4 = (long)BB * SS * HH / 4;
    const int prep_a_blocks = (int)((2 * E4 + 255) / 256);
    k_prep_a<<<prep_a_blocks, 256>>>(statp, dynp);

    k_gru<<<BB, 256>>>(din, lasth, embW, embb, Wih, Whh, bih, bhh, attnW,
                       hid_out, write_hidden);

    dim3 g(8, BB);  // 8 M-tiles of 128 rows, 128 batches
    k_gemm<512, 768><<<g, 256, SMEM_GEMM>>>(pA16_s, pA16_d,
                                            pWh_a, pWl_a, p_bias_attn, attnv, p_scores);

    k_ctx<<<BB, 256>>>(statp, decW);

    k_gemm<256, 512><<<g, 256, SMEM_GEMM>>>(pA16_s, pA16_s,
                                            pWh_d, pWl_d, p_bias_dec, decv, p_oscores);

    k_softmax_out<<<BB, 256>>>(out);
}

// round 10
// speedup vs baseline: 2.1758x; 1.4361x over previous
#include <cuda_runtime.h>
#include <cuda_fp16.h>
#include <math.h>
#include <stdint.h>

// Shapes (fixed by the problem)
#define BB 128
#define SS 1000
#define HH 256
#define SP 1024

// ---------------- scratch (device globals; no allocations allowed) ----------
__device__ float g_bias_attn[BB * 768];
__device__ float g_scores[BB * SP];
__device__ float g_bias_dec[BB * 512];
__device__ float g_oscores[BB * SP];
// Weights as single fp16, K-packed rows
__device__ __half g_Wh_a[768 * 512];
__device__ __half g_Wh_d[512 * 256];
// Activations as single fp16: [b][s][k]
__device__ __half g_A16_s[BB * SS * HH];
__device__ __half g_A16_d[BB * SS * HH];

// ============================================================================
// Baseline-PTX helpers (compile under compute_103: mma.sync / ldmatrix / cp.async)
// ============================================================================
__device__ __forceinline__ uint32_t smem_u32(const void* p) {
    uint32_t a;
    asm("{ .reg .u64 t; cvta.to.shared.u64 t, %1; cvt.u32.u64 %0, t; }" : "=r"(a) : "l"(p));
    return a;
}
__device__ __forceinline__ void ldm4(uint32_t* r, uint32_t addr) {
    asm volatile("ldmatrix.sync.aligned.m8n8.x4.shared.b16 {%0,%1,%2,%3}, [%4];"
                 : "=r"(r[0]), "=r"(r[1]), "=r"(r[2]), "=r"(r[3]) : "r"(addr));
}
__device__ __forceinline__ void mma_f16(float* c, const uint32_t* a, uint32_t b0, uint32_t b1) {
    asm volatile("mma.sync.aligned.m16n8k16.row.col.f32.f16.f16.f32 "
                 "{%0,%1,%2,%3}, {%4,%5,%6,%7}, {%8,%9}, {%0,%1,%2,%3};"
                 : "+f"(c[0]), "+f"(c[1]), "+f"(c[2]), "+f"(c[3])
                 : "r"(a[0]), "r"(a[1]), "r"(a[2]), "r"(a[3]), "r"(b0), "r"(b1));
}
__device__ __forceinline__ void cpa16(uint32_t dst, const void* src) {
    asm volatile("cp.async.cg.shared.global [%0], [%1], 16;" :: "r"(dst), "l"(src));
}
#define CP_COMMIT() asm volatile("cp.async.commit_group;" ::: "memory")
#define CP_WAIT2()  asm volatile("cp.async.wait_group 2;" ::: "memory")

// ============================================================================
// Kernel 0a: convert weights to fp16 (K-packed)
// ============================================================================
__global__ __launch_bounds__(256) void k_prep_w(const float* __restrict__ attnW,
                                                const float* __restrict__ decW) {
    const int i = blockIdx.x * 256 + threadIdx.x;
    if (i < 768 * 512) {
        const int j = i >> 9, k = i & 511;
        g_Wh_a[i] = __float2half_rn(attnW[j * 768 + k]);
    } else if (i < 768 * 512 + 512 * 256) {
        const int t = i - 768 * 512;
        const int j = t >> 8, k = t & 255;
        g_Wh_d[t] = __float2half_rn(decW[j * 512 + k]);
    }
}

// ============================================================================
// Kernel 0b: convert static/dynamic to fp16 (single array each)
// ============================================================================
__global__ __launch_bounds__(256) void k_prep_a(const float* __restrict__ statp,
                                                const float* __restrict__ dynp) {
    const long E4 = (long)BB * SS * HH / 4;   // float4 count per tensor
    long i = (long)blockIdx.x * 256 + threadIdx.x;
    if (i >= 2 * E4) return;
    const bool dyn = (i >= E4);
    const long j = dyn ? i - E4 : i;
    const float4 x = reinterpret_cast<const float4*>(dyn ? dynp : statp)[j];
    __half2 lo = __floats2half2_rn(x.x, x.y);
    __half2 hi = __floats2half2_rn(x.z, x.w);
    uint2* dst = reinterpret_cast<uint2*>(dyn ? g_A16_d : g_A16_s);
    dst[j] = make_uint2(*(const unsigned*)&lo, *(const unsigned*)&hi);
}

// ============================================================================
// Kernel 1: embed + GRU cell + bias_attn  (fp32, unchanged)
// ============================================================================
__global__ __launch_bounds__(256) void k_gru(
    const float* __restrict__ din, const float* __restrict__ lasth,
    const float* __restrict__ embW, const float* __restrict__ embb,
    const float* __restrict__ Wih, const float* __restrict__ Whh,
    const float* __restrict__ bih, const float* __restrict__ bhh,
    const float* __restrict__ attnW, float* __restrict__ hid_out, int write_hidden) {
    const int b = blockIdx.x;
    const int t = threadIdx.x;

    __shared__ __align__(16) float emb[HH];
    __shared__ __align__(16) float hold[HH];
    __shared__ __align__(16) float hnew[HH];

    const float d0 = din[b * 2 + 0];
    const float d1 = din[b * 2 + 1];
    emb[t]  = d0 * embW[t * 2 + 0] + d1 * embW[t * 2 + 1] + embb[t];
    hold[t] = lasth[b * HH + t];
    __syncthreads();

    float gx[3], gh[3];
#pragma unroll
    for (int g = 0; g < 3; g++) { gx[g] = bih[g * HH + t]; gh[g] = bhh[g * HH + t]; }
#pragma unroll
    for (int g = 0; g < 3; g++) {
        const float4* wi = reinterpret_cast<const float4*>(Wih + (g * HH + t) * HH);
        const float4* wh = reinterpret_cast<const float4*>(Whh + (g * HH + t) * HH);
        const float4* ev = reinterpret_cast<const float4*>(emb);
        const float4* hv = reinterpret_cast<const float4*>(hold);
        float sx = 0.f, sh = 0.f;
#pragma unroll 4
        for (int k = 0; k < HH / 4; k++) {
            float4 a = wi[k], c = wh[k], e = ev[k], h4 = hv[k];
            sx += a.x * e.x + a.y * e.y + a.z * e.z + a.w * e.w;
            sh += c.x * h4.x + c.y * h4.y + c.z * h4.z + c.w * h4.w;
        }
        gx[g] += sx; gh[g] += sh;
    }

    const float r = 1.f / (1.f + expf(-(gx[0] + gh[0])));
    const float z = 1.f / (1.f + expf(-(gx[1] + gh[1])));
    const float n = tanhf(gx[2] + r * gh[2]);
    const float hv = (1.f - z) * n + z * hold[t];
    hnew[t] = hv;
    if (write_hidden) hid_out[b * HH + t] = hv;
    __syncthreads();

    const float4* hv4 = reinterpret_cast<const float4*>(hnew);
#pragma unroll
    for (int g = 0; g < 3; g++) {
        const int j = g * HH + t;
        const float4* w = reinterpret_cast<const float4*>(attnW + j * 768 + 512);
        float s = 0.f;
#pragma unroll 4
        for (int k = 0; k < HH / 4; k++) {
            float4 ww = w[k], hh = hv4[k];
            s += ww.x * hh.x + ww.y * hh.y + ww.z * hh.z + ww.w * hh.w;
        }
        g_bias_attn[b * 768 + j] = s;
    }
}

// ============================================================================
// Kernel 2/4: fused score GEMM on HMMA (single fp16 term, fp32 accum)
//   score[b,s] = sum_j v[j] * tanh( sum_k A[b,s,k]*W[j,k] + bias[b,j] )
// R6/R9 skeleton: block 128 rows x full N, 8 warps = 4(M) x 2(N), tile 32x64.
// Single fp16 mma term (A fp16, W fp16): -50% tensor work vs R9.  Two smem
// tiles per chunk (A, W), K chunks of 64, THREE-stage cp.async pipeline
// (wait_group 2), row stride 72 fp16 (144B, conflict-free).
// smem = 3 x 36864 + 1KB = 111.6KB -> 2 CTAs/SM (221KB <= 228KB).
// ============================================================================
#define KCH   64
#define TSTR  72
#define TILE_B (128 * TSTR * 2)   // 18432 bytes
#define A_OFF  0
#define W_OFF  TILE_B
#define BUF_B  (2 * TILE_B)       // 36864 bytes
#define SMEM_GEMM (3 * BUF_B + 1024)

template <int K, int N>
__global__ __launch_bounds__(256, 2) void k_gemm(
    const __half* __restrict__ A16_s, const __half* __restrict__ A16_d,
    const __half* __restrict__ Wh,
    const float* __restrict__ bias, const float* __restrict__ v,
    float* __restrict__ scores) {
    constexpr int KC = K / KCH;     // 8 or 4
    constexpr int NT = N / 128;     // 6 or 4
    constexpr int NC = NT * KC;

    extern __shared__ char sm[];
    const uint32_t su = smem_u32(sm);
    float* sred = (float*)(sm + 3 * BUF_B);

    const int tid = threadIdx.x, lane = tid & 31, wid = tid >> 5;
    const int wm = wid & 3, wn = wid >> 2;
    const int b = blockIdx.y, s0 = blockIdx.x * 128;

    // cp.async: thread covers (row = tid/2, 32-elem half = tid&1); 4x16B each
    const int cr = tid >> 1, ch = tid & 1;
    const long abase = ((long)b * SS + min(s0 + cr, SS - 1)) * HH + ch * 32;
    const uint32_t cd = (uint32_t)((cr * TSTR + ch * 32) * 2);

    auto issue = [&](int c) {
        if (c < NC) {
            const int nt = c / KC, kc = c - nt * KC;
            const __half* asrc;
            int kofs;
            if (K == 512 && kc >= 4) { asrc = A16_d; kofs = (kc - 4) * KCH; }
            else                     { asrc = A16_s; kofs = kc * KCH; }
            const __half* pa = asrc + abase + kofs;
            const long wrow = (long)(nt * 128 + cr) * K + kc * KCH + ch * 32;
            const uint32_t d = su + (uint32_t)(c % 3) * BUF_B + cd;
#pragma unroll
            for (int q = 0; q < 4; q++) {
                cpa16(d + A_OFF + q * 16, pa + q * 8);
                cpa16(d + W_OFF + q * 16, Wh + wrow + q * 8);
            }
        }
    };

    // ldmatrix per-thread base offsets (bytes), within a buffer
    const uint32_t a_sm = (uint32_t)((wm * 32 + (lane & 15)) * (TSTR * 2) + ((lane >> 4) & 1) * 16);
    const uint32_t w_sm = (uint32_t)((wn * 64 + (lane & 7) + ((lane & 16) >> 1)) * (TSTR * 2) + (lane & 8) * 2);

    float part[4] = {0.f, 0.f, 0.f, 0.f};

    issue(0); CP_COMMIT();
    issue(1); CP_COMMIT();
    issue(2); CP_COMMIT();

    float acc[2][8][4];

    for (int c = 0; c < NC; c++) {
        const int kc = c % KC;
        const int nt = c / KC;
        if (kc == 0) {
#pragma unroll
            for (int i = 0; i < 2; i++)
#pragma unroll
                for (int j = 0; j < 8; j++)
#pragma unroll
                    for (int q = 0; q < 4; q++) acc[i][j][q] = 0.f;
        }

        CP_WAIT2();          // chunk c landed (<=2 newer groups in flight)
        __syncthreads();

        const uint32_t bo = su + (uint32_t)(c % 3) * BUF_B;
#pragma unroll
        for (int ks = 0; ks < 4; ks++) {
            const uint32_t ko = (uint32_t)(ks * 32);  // 16 elems * 2B
            uint32_t af[2][4];
#pragma unroll
            for (int mi = 0; mi < 2; mi++)
                ldm4(af[mi], bo + A_OFF + a_sm + (uint32_t)(mi * 16 * TSTR * 2) + ko);
#pragma unroll
            for (int ng = 0; ng < 4; ng++) {
                uint32_t wf[4];
                ldm4(wf, bo + W_OFF + w_sm + (uint32_t)(ng * 16 * TSTR * 2) + ko);
#pragma unroll
                for (int mi = 0; mi < 2; mi++) {
                    mma_f16(acc[mi][2 * ng],     af[mi], wf[0], wf[1]);
                    mma_f16(acc[mi][2 * ng + 1], af[mi], wf[2], wf[3]);
                }
            }
        }
        __syncthreads();     // buf c%3 fully consumed by all warps
        issue(c + 3);        // refill buf c%3
        CP_COMMIT();

        if (kc == KC - 1) {
            // ---- epilogue for this N tile: tanh + v-dot, register-only ----
            const int jb = nt * 128 + wn * 64 + 2 * (lane & 3);
#pragma unroll
            for (int n8 = 0; n8 < 8; n8++) {
                const int j = jb + n8 * 8;
                const float2 bv = *reinterpret_cast<const float2*>(&bias[(long)b * N + j]);
                const float2 vv = *reinterpret_cast<const float2*>(&v[j]);
#pragma unroll
                for (int mi = 0; mi < 2; mi++) {
                    part[mi * 2 + 0] += vv.x * tanhf(acc[mi][n8][0] + bv.x)
                                      + vv.y * tanhf(acc[mi][n8][1] + bv.y);
                    part[mi * 2 + 1] += vv.x * tanhf(acc[mi][n8][2] + bv.x)
                                      + vv.y * tanhf(acc[mi][n8][3] + bv.y);
                }
            }
        }
    }

    // reduce across the 4 lanes sharing a row (lane bits 0,1)
#pragma unroll
    for (int i = 0; i < 4; i++) {
        part[i] += __shfl_xor_sync(0xffffffffu, part[i], 1);
        part[i] += __shfl_xor_sync(0xffffffffu, part[i], 2);
    }
    if ((lane & 3) == 0) {
        const int r = lane >> 2;
        const int base = wn * 128 + wm * 32;
        sred[base + r]      = part[0];
        sred[base + r + 8]  = part[1];
        sred[base + r + 16] = part[2];
        sred[base + r + 24] = part[3];
    }
    __syncthreads();
    if (tid < 128) {
        const int s = s0 + tid;
        if (s < SS) scores[b * SP + s] = sred[tid] + sred[128 + tid];
    }
}

// ============================================================================
// Kernel 3: softmax(scores) -> context -> bias_dec  (fp32, unchanged)
// ============================================================================
__global__ __launch_bounds__(256) void k_ctx(
    const float* __restrict__ statp, const float* __restrict__ decW) {
    const int b = blockIdx.x;
    const int t = threadIdx.x;

    __shared__ float attn[SP];
    __shared__ float red[256];
    __shared__ __align__(16) float ctx[HH];

    float m = -1e30f;
    for (int s = t; s < SS; s += 256) m = fmaxf(m, g_scores[b * SP + s]);
    red[t] = m; __syncthreads();
    for (int o = 128; o; o >>= 1) { if (t < o) red[t] = fmaxf(red[t], red[t + o]); __syncthreads(); }
    m = red[0]; __syncthreads();

    float lsum = 0.f;
    for (int s = t; s < SS; s += 256) {
        const float e = expf(g_scores[b * SP + s] - m);
        attn[s] = e; lsum += e;
    }
    red[t] = lsum; __syncthreads();
    for (int o = 128; o; o >>= 1) { if (t < o) red[t] += red[t + o]; __syncthreads(); }
    const float inv = 1.f / red[0];
    __syncthreads();

    const float* sp = statp + (long)b * SS * HH + t;
    float c0 = 0.f, c1 = 0.f, c2 = 0.f, c3 = 0.f;
    int s = 0;
    for (; s + 3 < SS; s += 4) {
        c0 += attn[s + 0] * sp[(s + 0) * HH];
        c1 += attn[s + 1] * sp[(s + 1) * HH];
        c2 += attn[s + 2] * sp[(s + 2) * HH];
        c3 += attn[s + 3] * sp[(s + 3) * HH];
    }
    for (; s < SS; s++) c0 += attn[s] * sp[s * HH];
    ctx[t] = (c0 + c1 + c2 + c3) * inv;
    __syncthreads();

    const float4* cv = reinterpret_cast<const float4*>(ctx);
#pragma unroll
    for (int g = 0; g < 2; g++) {
        const int j = g * HH + t;
        const float4* w = reinterpret_cast<const float4*>(decW + j * 512 + 256);
        float sacc = 0.f;
#pragma unroll 4
        for (int k = 0; k < HH / 4; k++) {
            float4 ww = w[k], cc = cv[k];
            sacc += ww.x * cc.x + ww.y * cc.y + ww.z * cc.z + ww.w * cc.w;
        }
        g_bias_dec[b * 512 + j] = sacc;
    }
}

// ============================================================================
// Kernel 5: final softmax -> outputs [B,S]
// ============================================================================
__global__ __launch_bounds__(256) void k_softmax_out(float* __restrict__ out) {
    const int b = blockIdx.x;
    const int t = threadIdx.x;
    __shared__ float e_s[SP];
    __shared__ float red[256];

    float m = -1e30f;
    for (int s = t; s < SS; s += 256) m = fmaxf(m, g_oscores[b * SP + s]);
    red[t] = m; __syncthreads();
    for (int o = 128; o; o >>= 1) { if (t < o) red[t] = fmaxf(red[t], red[t + o]); __syncthreads(); }
    m = red[0]; __syncthreads();

    float lsum = 0.f;
    for (int s = t; s < SS; s += 256) {
        const float e = expf(g_oscores[b * SP + s] - m);
        e_s[s] = e; lsum += e;
    }
    red[t] = lsum; __syncthreads();
    for (int o = 128; o; o >>= 1) { if (t < o) red[t] += red[t + o]; __syncthreads(); }
    const float inv = 1.f / red[0];
    __syncthreads();

    for (int s = t; s < SS; s += 256) out[b * SS + s] = e_s[s] * inv;
}

// ============================================================================
// Launch
// ============================================================================
extern "C" void kernel_launch(void* const* d_in, const int* in_sizes, int n_in,
                              void* d_out, int out_size) {
    const float* din   = (const float*)d_in[0];
    const float* lasth = (const float*)d_in[1];
    const float* statp = (const float*)d_in[2];
    const float* dynp  = (const float*)d_in[3];
    const float* embW  = (const float*)d_in[4];
    const float* embb  = (const float*)d_in[5];
    const float* Wih   = (const float*)d_in[6];
    const float* Whh   = (const float*)d_in[7];
    const float* bih   = (const float*)d_in[8];
    const float* bhh   = (const float*)d_in[9];
    const float* attnW = (const float*)d_in[10];
    const float* attnv = (const float*)d_in[11];
    const float* decW  = (const float*)d_in[12];
    const float* decv  = (const float*)d_in[13];
    float* out = (float*)d_out;

    const int write_hidden = (out_size >= BB * SS + BB * HH) ? 1 : 0;
    float* hid_out = out + BB * SS;

    float *p_bias_attn, *p_scores, *p_bias_dec, *p_oscores;
    __half *pWh_a, *pWh_d, *pA16_s, *pA16_d;
    cudaGetSymbolAddress((void**)&p_bias_attn, g_bias_attn);
    cudaGetSymbolAddress((void**)&p_scores,    g_scores);
    cudaGetSymbolAddress((void**)&p_bias_dec,  g_bias_dec);
    cudaGetSymbolAddress((void**)&p_oscores,   g_oscores);
    cudaGetSymbolAddress((void**)&pWh_a, g_Wh_a);
    cudaGetSymbolAddress((void**)&pWh_d, g_Wh_d);
    cudaGetSymbolAddress((void**)&pA16_s, g_A16_s);
    cudaGetSymbolAddress((void**)&pA16_d, g_A16_d);

    cudaFuncSetAttribute(k_gemm<512, 768>, cudaFuncAttributeMaxDynamicSharedMemorySize, SMEM_GEMM);
    cudaFuncSetAttribute(k_gemm<256, 512>, cudaFuncAttributeMaxDynamicSharedMemorySize, SMEM_GEMM);

    const int prep_w_blocks = (768 * 512 + 512 * 256 + 255) / 256;
    k_prep_w<<<prep_w_blocks, 256>>>(attnW, decW);

    const long E4 = (long)BB * SS * HH / 4;
    const int prep_a_blocks = (int)((2 * E4 + 255) / 256);
    k_prep_a<<<prep_a_blocks, 256>>>(statp, dynp);

    k_gru<<<BB, 256>>>(din, lasth, embW, embb, Wih, Whh, bih, bhh, attnW,
                       hid_out, write_hidden);

    dim3 g(8, BB);  // 8 M-tiles of 128 rows, 128 batches
    k_gemm<512, 768><<<g, 256, SMEM_GEMM>>>(pA16_s, pA16_d,
                                            pWh_a, p_bias_attn, attnv, p_scores);

    k_ctx<<<BB, 256>>>(statp, decW);

    k_gemm<256, 512><<<g, 256, SMEM_GEMM>>>(pA16_s, pA16_s,
                                            pWh_d, p_bias_dec, decv, p_oscores);

    k_softmax_out<<<BB, 256>>>(out);
}